// round 3
// baseline (speedup 1.0000x reference)
#include <cuda_runtime.h>
#include <cuda_fp16.h>
#include <cstdint>

#define BATCH   8192
#define HID     2560
#define NGATE   10240
#define NUM_KS  80
#define MT      64      // M tiles of 128
#define NT      40      // N tiles of 256 gate cols

#define A_TILE   16384
#define B_TILE   32768
#define STAGE_SZ 49152
#define SM_C0    147456   // 128 x 68 f32 = 34816
#define SM_BIAS  182272   // 256 f32
#define SM_BAR   183296
#define SMEM_TOT 183360

__device__ __align__(1024) unsigned char g_A[(size_t)MT * NUM_KS * A_TILE];
__device__ __align__(1024) unsigned char g_B[(size_t)NT * NUM_KS * B_TILE];
__device__ float g_bias[NGATE];

static __device__ __forceinline__ uint32_t smem_u32(const void* p) {
    uint32_t a;
    asm("{ .reg .u64 t; cvta.to.shared.u64 t, %1; cvt.u32.u64 %0, t; }" : "=r"(a) : "l"(p));
    return a;
}

#define MBAR_INIT(addr, cnt) \
    asm volatile("mbarrier.init.shared.b64 [%0], %1;" :: "r"(addr), "r"(cnt) : "memory")
#define MBAR_EXPECT_TX(addr, bytes) \
    asm volatile("mbarrier.arrive.expect_tx.shared.b64 _, [%0], %1;" :: "r"(addr), "r"(bytes) : "memory")
#define MBAR_ARRIVE(addr) \
    asm volatile("mbarrier.arrive.shared.b64 _, [%0];" :: "r"(addr) : "memory")

#define MBAR_WAIT(addr, ph) do {                                                    \
    uint32_t _m = (addr); uint32_t _p = (ph); uint32_t _d;                          \
    asm volatile("{\n\t.reg .pred p;\n\t"                                           \
        "mbarrier.try_wait.parity.acquire.cta.shared::cta.b64 p, [%1], %2;\n\t"     \
        "selp.b32 %0, 1, 0, p;\n\t}" : "=r"(_d) : "r"(_m), "r"(_p) : "memory");     \
    if (!_d) {                                                                      \
        asm volatile("{\n\t.reg .pred P1;\n\t"                                      \
            "WL_%=:\n\t"                                                            \
            "mbarrier.try_wait.parity.acquire.cta.shared::cta.b64 P1, [%0], %1, 0x989680;\n\t" \
            "@P1 bra.uni WD_%=;\n\tbra.uni WL_%=;\n\tWD_%=:\n\t}"                   \
            :: "r"(_m), "r"(_p) : "memory");                                        \
    }                                                                               \
} while (0)

static __device__ __forceinline__ void bulk_g2s(uint32_t sdst, const void* gsrc,
                                                uint32_t bytes, uint32_t mbar) {
    asm volatile(
        "cp.async.bulk.shared::cluster.global.mbarrier::complete_tx::bytes [%0], [%1], %2, [%3];"
        :: "r"(sdst), "l"(gsrc), "r"(bytes), "r"(mbar) : "memory");
}

#define LDSM4(r, addr)                                                              \
    asm volatile("ldmatrix.sync.aligned.m8n8.x4.shared.b16 {%0,%1,%2,%3}, [%4];"    \
        : "=r"((r)[0]), "=r"((r)[1]), "=r"((r)[2]), "=r"((r)[3]) : "r"(addr))

#define MMA16816(d, a, b0, b1)                                                      \
    asm volatile("mma.sync.aligned.m16n8k16.row.col.f32.f16.f16.f32 "               \
        "{%0,%1,%2,%3},{%4,%5,%6,%7},{%8,%9},{%0,%1,%2,%3};"                        \
        : "+f"((d)[0]), "+f"((d)[1]), "+f"((d)[2]), "+f"((d)[3])                    \
        : "r"((a)[0]), "r"((a)[1]), "r"((a)[2]), "r"((a)[3]), "r"(b0), "r"(b1))

static __device__ __forceinline__ float ftanh(float x) {
    float ax = fabsf(x);
    float e  = __expf(-2.0f * ax);
    float t  = __fdividef(1.0f - e, 1.0f + e);
    return copysignf(t, x);
}
static __device__ __forceinline__ float fsig(float x) {
    return fmaf(0.5f, ftanh(0.5f * x), 0.5f);
}

// ---- prep A: fp32 concat(input,h0) -> fp16 tiles 128 rows x 64 K, SW128 ----
__global__ __launch_bounds__(256) void prep_a(const float* __restrict__ inp,
                                              const float* __restrict__ h0) {
    int ks = blockIdx.x, mt = blockIdx.y;
    int kbase = ks * 64;
    const float* src = (kbase < HID) ? (inp + kbase) : (h0 + (kbase - HID));
    unsigned char* dst = g_A + (size_t)(mt * NUM_KS + ks) * A_TILE;
    int tid = threadIdx.x;
#pragma unroll 8
    for (int it = 0; it < 16; it++) {
        int idx = it * 256 + tid;
        int r = idx >> 5, kk2 = idx & 31;
        int m = mt * 128 + r;
        float2 v = *reinterpret_cast<const float2*>(src + (size_t)m * HID + 2 * kk2);
        __half2 h = __floats2half2_rn(v.x, v.y);
        uint32_t off = (uint32_t)(r * 128 + kk2 * 4);
        uint32_t sw = off ^ ((off >> 3) & 0x70);
        *reinterpret_cast<__half2*>(dst + sw) = h;
    }
}

// ---- prep B: gate-permuted K-major fp16 tiles 256 rows(N) x 64 K, SW128 ----
// permuted n = 4*(512p+j)+q  <-  original col = 2048p + 512q + j
__global__ __launch_bounds__(256) void prep_b(const float* __restrict__ wih,
                                              const float* __restrict__ whh) {
    __shared__ __half sm[64 * 258];
    int ks = blockIdx.x, nt = blockIdx.y;
    int tid = threadIdx.x;
    int n = nt * 256 + tid;
    int p = n >> 11, rem = n & 2047, j = rem >> 2, q = n & 3;
    int col = (p << 11) + (q << 9) + j;
    int kbase = ks * 64;
    const float* src = (kbase < HID) ? (wih + (size_t)kbase * NGATE)
                                     : (whh + (size_t)(kbase - HID) * NGATE);
#pragma unroll 4
    for (int it = 0; it < 64; it++) {
        float v = src[(size_t)it * NGATE + col];
        sm[it * 258 + tid] = __float2half_rn(v);
    }
    __syncthreads();
    unsigned char* dst = g_B + (size_t)(nt * NUM_KS + ks) * B_TILE;
#pragma unroll 8
    for (int it = 0; it < 32; it++) {
        int idx = it * 256 + tid;
        int nl = idx >> 5, kp = idx & 31;
        __half a = sm[(2 * kp) * 258 + nl];
        __half b = sm[(2 * kp + 1) * 258 + nl];
        uint32_t off = (uint32_t)(nl * 128 + kp * 4);
        uint32_t sw = off ^ ((off >> 3) & 0x70);
        *reinterpret_cast<__half2*>(dst + sw) = __halves2half2(a, b);
    }
}

__global__ __launch_bounds__(256) void prep_bias(const float* __restrict__ bih,
                                                 const float* __restrict__ bhh) {
    int n = blockIdx.x * 256 + threadIdx.x;
    int p = n >> 11, rem = n & 2047, j = rem >> 2, q = n & 3;
    int col = (p << 11) + (q << 9) + j;
    g_bias[n] = bih[col] + bhh[col];
}

// ---- fused HMMA GEMM (128M x 256 gate cols) + LSTM epilogue ----
__global__ __launch_bounds__(288, 1) void lstm_gemm(const float* __restrict__ c0,
                                                    float* __restrict__ out) {
    extern __shared__ __align__(1024) unsigned char smem[];
    uint32_t sb = smem_u32(smem);
    int tid = threadIdx.x;
    int lane = tid & 31;
    int wid = tid >> 5;
    int nt = blockIdx.x, mt = blockIdx.y;
    int m0 = mt * 128, co0 = nt * 64;

    if (tid == 0) {
#pragma unroll
        for (int s = 0; s < 3; s++) {
            MBAR_INIT(sb + SM_BAR + s * 8, 1);        // full[s], tx-based
            MBAR_INIT(sb + SM_BAR + 24 + s * 8, 8);   // empty[s], 8 warps
        }
    }
    __syncthreads();

    float acc[4][8][4];
#pragma unroll
    for (int a = 0; a < 4; a++)
#pragma unroll
        for (int b = 0; b < 8; b++)
#pragma unroll
            for (int cI = 0; cI < 4; cI++) acc[a][b][cI] = 0.0f;

    if (wid == 8) {
        // ---------------- producer warp ----------------
        if (lane == 0) {
            const unsigned char* Ab = g_A + (size_t)mt * NUM_KS * A_TILE;
            const unsigned char* Bb = g_B + (size_t)nt * NUM_KS * B_TILE;
            int slot = 0; uint32_t pph = 1;
            for (int s = 0; s < NUM_KS; s++) {
                MBAR_WAIT(sb + SM_BAR + 24 + slot * 8, pph);
                uint32_t full = sb + SM_BAR + slot * 8;
                MBAR_EXPECT_TX(full, STAGE_SZ);
                uint32_t dst = sb + slot * STAGE_SZ;
                bulk_g2s(dst,         Ab + (size_t)s * A_TILE, A_TILE, full);
                bulk_g2s(dst + 16384, Bb + (size_t)s * B_TILE, B_TILE, full);
                if (++slot == 3) { slot = 0; pph ^= 1; }
            }
        }
    } else {
        // ---------------- compute warps: prefetch c0/bias ----------------
        float* c0s = reinterpret_cast<float*>(smem + SM_C0);
#pragma unroll
        for (int it = 0; it < 8; it++) {
            int idx = it * 256 + tid;
            int r = idx >> 4, c4 = idx & 15;
            float4 v = *reinterpret_cast<const float4*>(c0 + (size_t)(m0 + r) * HID + co0 + c4 * 4);
            float* d = c0s + r * 68 + c4 * 4;
            d[0] = v.x; d[1] = v.y; d[2] = v.z; d[3] = v.w;
        }
        if (tid < 64) {
            float4 bv = *reinterpret_cast<const float4*>(g_bias + nt * 256 + tid * 4);
            float* d = reinterpret_cast<float*>(smem + SM_BIAS) + tid * 4;
            d[0] = bv.x; d[1] = bv.y; d[2] = bv.z; d[3] = bv.w;
        }

        // ---------------- mainloop ----------------
        int wm = wid & 1, wn = wid >> 1;
        uint32_t arow   = (uint32_t)(wm * 64 + (lane & 15));
        uint32_t apatch = (arow & 7) << 4;
        uint32_t abyte  = (uint32_t)((lane >> 4) * 16);
        uint32_t aoff0  = arow * 128;
        uint32_t gq     = (uint32_t)(lane >> 3);
        uint32_t brow0  = (uint32_t)(wn * 64 + ((gq >> 1) * 8) + (lane & 7));
        uint32_t bpatch = (brow0 & 7) << 4;
        uint32_t bbyte  = (gq & 1) * 16;
        uint32_t boff0  = 16384 + brow0 * 128;

        int slot = 0; uint32_t ph = 0;
#pragma unroll 1
        for (int s = 0; s < NUM_KS; s++) {
            MBAR_WAIT(sb + SM_BAR + slot * 8, ph);
            uint32_t st = sb + slot * STAGE_SZ;
#pragma unroll
            for (int kg = 0; kg < 4; kg++) {
                uint32_t kb = (uint32_t)(kg * 32);
                uint32_t af[4][4], bf[4][4];
#pragma unroll
                for (int mi = 0; mi < 4; mi++) {
                    uint32_t addr = st + aoff0 + mi * 2048 + ((abyte + kb) ^ apatch);
                    LDSM4(af[mi], addr);
                }
#pragma unroll
                for (int ni2 = 0; ni2 < 4; ni2++) {
                    uint32_t addr = st + boff0 + ni2 * 2048 + ((bbyte + kb) ^ bpatch);
                    LDSM4(bf[ni2], addr);
                }
#pragma unroll
                for (int mi = 0; mi < 4; mi++)
#pragma unroll
                    for (int ni = 0; ni < 8; ni++)
                        MMA16816(acc[mi][ni], af[mi], bf[ni >> 1][(ni & 1) * 2],
                                 bf[ni >> 1][(ni & 1) * 2 + 1]);
            }
            if (lane == 0) MBAR_ARRIVE(sb + SM_BAR + 24 + slot * 8);
            if (++slot == 3) { slot = 0; ph ^= 1; }
        }
    }

    __syncthreads();

    // ---------------- epilogue: acc -> smem -> LSTM -> out ----------------
    float* gsm = reinterpret_cast<float*>(smem);
    const float* bs  = reinterpret_cast<const float*>(smem + SM_BIAS);
    const float* c0s = reinterpret_cast<const float*>(smem + SM_C0);
    float* outh = out;
    float* outc = out + (size_t)BATCH * HID;

#pragma unroll 1
    for (int chunk = 0; chunk < 2; chunk++) {
        if (wid < 8 && ((wid >> 1) >> 1) == chunk) {
            int wm = wid & 1, wn = wid >> 1;
            int colb = (wn & 1) * 64;
#pragma unroll
            for (int mi = 0; mi < 4; mi++)
#pragma unroll
                for (int ni = 0; ni < 8; ni++)
#pragma unroll
                    for (int r = 0; r < 4; r++) {
                        int row = wm * 64 + mi * 16 + (lane >> 2) + 8 * (r >> 1);
                        int col = colb + ni * 8 + 2 * (lane & 3) + (r & 1);
                        gsm[row * 132 + col] = acc[mi][ni][r];
                    }
        }
        __syncthreads();
        if (tid < 256) {
#pragma unroll 1
            for (int it = 0; it < 4; it++) {
                int task = it * 256 + tid;
                int og = task & 7, row = task >> 3;
                float h4[4], c4[4];
#pragma unroll
                for (int u = 0; u < 4; u++) {
                    const float* gp = &gsm[row * 132 + 16 * og + 4 * u];
                    float4 gv = *reinterpret_cast<const float4*>(gp);
                    float4 bq = *reinterpret_cast<const float4*>(&bs[chunk * 128 + 16 * og + 4 * u]);
                    float cc = c0s[row * 68 + chunk * 32 + og * 4 + u];
                    float g = gv.x + bq.x;
                    float i = gv.y + bq.y;
                    float f = gv.z + bq.z;
                    float o = gv.w + bq.w;
                    float c1 = ftanh(g) * fsig(i) + cc * fsig(f);
                    c4[u] = c1;
                    h4[u] = ftanh(c1) * fsig(o);
                }
                size_t base = (size_t)(m0 + row) * HID + co0 + chunk * 32 + og * 4;
                *reinterpret_cast<float4*>(outh + base) = make_float4(h4[0], h4[1], h4[2], h4[3]);
                *reinterpret_cast<float4*>(outc + base) = make_float4(c4[0], c4[1], c4[2], c4[3]);
            }
        }
        __syncthreads();
    }
}

extern "C" void kernel_launch(void* const* d_in, const int* in_sizes, int n_in,
                              void* d_out, int out_size) {
    const float* input = (const float*)d_in[0];
    const float* h0    = (const float*)d_in[1];
    const float* c0    = (const float*)d_in[2];
    const float* wih   = (const float*)d_in[3];
    const float* whh   = (const float*)d_in[4];
    const float* bih   = (const float*)d_in[5];
    const float* bhh   = (const float*)d_in[6];
    float* out = (float*)d_out;

    cudaFuncSetAttribute(lstm_gemm, cudaFuncAttributeMaxDynamicSharedMemorySize, SMEM_TOT);

    prep_a<<<dim3(NUM_KS, MT), 256>>>(input, h0);
    prep_b<<<dim3(NUM_KS, NT), 256>>>(wih, whh);
    prep_bias<<<NGATE / 256, 256>>>(bih, bhh);
    lstm_gemm<<<dim3(NT, MT), 288, SMEM_TOT>>>(c0, out);
}